// round 7
// baseline (speedup 1.0000x reference)
#include <cuda_runtime.h>
#include <cuda_bf16.h>
#include <cstdint>

#define NN 100000
#define EE 1600000
#define DD 128
#define GG 64
#define NPART 296

#define SA_ST 132
#define SW_ST 136

// ---------------- device scratch ----------------
__device__ unsigned g_xh[(size_t)NN * DD / 2];   // bf16x2 scaled input features (layer-1 gather source)
__device__ unsigned g_xh2[(size_t)NN * DD / 2];  // bf16x2 layer-1 output (layer-2 / gemm2 source)
__device__ float    g_w[(size_t)NN * GG];        // per-(src,graph) pooling weights
__device__ unsigned g_w1t[DD * DD];              // W1 pre-converted to tf32
__device__ float    g_pp[NPART][GG * DD];        // gemm2 partial sums
__device__ uint2    g_gd[NN];                    // packed {gid, ndst}
__device__ int      g_deg[2 * NN];               // [0,NN)=deg_out, [NN,2NN)=deg_in
__device__ float    g_nsrc[NN];
__device__ float    g_ndst[NN];
__device__ float    g_cnt[GG];
__device__ int      g_off[NN];
__device__ int      g_cursor[NN];
__device__ int      g_sorted[EE];
__device__ int      g_counter;

// ---------------- helpers ----------------
__device__ __forceinline__ unsigned f2tf32(float x) {
    unsigned r;
    asm("cvt.rna.tf32.f32 %0, %1;" : "=r"(r) : "f"(x));
    return r;
}
__device__ __forceinline__ unsigned pack_bf16x2(float lo, float hi) {
    unsigned r;
    asm("cvt.rn.bf16x2.f32 %0, %1, %2;" : "=r"(r) : "f"(hi), "f"(lo));
    return r;
}
__device__ __forceinline__ void mma_tf32(float& d0, float& d1, float& d2, float& d3,
                                         unsigned a0, unsigned a1, unsigned a2, unsigned a3,
                                         unsigned b0, unsigned b1) {
    asm("mma.sync.aligned.m16n8k8.row.col.f32.tf32.tf32.f32 "
        "{%0,%1,%2,%3}, {%4,%5,%6,%7}, {%8,%9}, {%0,%1,%2,%3};"
        : "+f"(d0), "+f"(d1), "+f"(d2), "+f"(d3)
        : "r"(a0), "r"(a1), "r"(a2), "r"(a3), "r"(b0), "r"(b1));
}
__device__ __forceinline__ float bf_lo(unsigned u) { return __uint_as_float(u << 16); }
__device__ __forceinline__ float bf_hi(unsigned u) { return __uint_as_float(u & 0xffff0000u); }
__device__ __forceinline__ void acc_bf16(float4& a, uint2 u) {
    a.x += bf_lo(u.x); a.y += bf_hi(u.x);
    a.z += bf_lo(u.y); a.w += bf_hi(u.y);
}

// ---------------- kernel 1: degree count + zero w/cnt/counter ----------------
__global__ void k_degree(const int* __restrict__ src, const int* __restrict__ dst, int E) {
    int i0 = blockIdx.x * blockDim.x + threadIdx.x;
    int stride = gridDim.x * blockDim.x;
    float4 z = make_float4(0.f, 0.f, 0.f, 0.f);
    for (int i = i0; i < NN * GG / 4; i += stride) ((float4*)g_w)[i] = z;
    if (i0 < GG) g_cnt[i0] = 0.f;
    if (i0 == GG) g_counter = 0;
    for (int i = i0; i < E; i += stride) {
        atomicAdd(&g_deg[src[i]], 1);
        atomicAdd(&g_deg[NN + dst[i]], 1);
    }
}

// ---------------- kernel 2: norms, gd pack, counts, offsets, W1->tf32 ----------------
__global__ void k_nodeprep(const int* __restrict__ gid, const float* __restrict__ W1, int N) {
    int i = blockIdx.x * blockDim.x + threadIdx.x;
    if (i < DD * DD) g_w1t[i] = f2tf32(W1[i]);
    if (i < N) {
        int dout = g_deg[i];
        int din = g_deg[NN + i];
        float ns = rsqrtf((float)max(dout, 1));
        float nd = rsqrtf((float)max(din, 1));
        g_nsrc[i] = ns;
        g_ndst[i] = nd;
        int g = gid[i];
        g_gd[i] = make_uint2((unsigned)g, __float_as_uint(nd));
        atomicAdd(&g_cnt[g], 1.f);
        int off = atomicAdd(&g_counter, din);   // arbitrary-order segment assignment
        g_off[i] = off;
        g_cursor[i] = off;
    }
}

// ---------------- kernel 3: scatter + wbuild (edges) and bf16 prep (nodes) ----------------
__global__ void k_edge_node(const int* __restrict__ src, const int* __restrict__ dst,
                            const float* __restrict__ x, int E, int N) {
    int i = blockIdx.x * blockDim.x + threadIdx.x;
    if (i < E) {
        int s = src[i];
        int d = dst[i];
        int p = atomicAdd(&g_cursor[d], 1);
        g_sorted[p] = s;
        uint2 gd = g_gd[d];
        atomicAdd(&g_w[(size_t)s * GG + gd.x], __uint_as_float(gd.y));
    } else {
        int j = i - E;                       // float4 index over node features
        if (j < N * 32) {
            int n = j >> 5;
            float sc = g_nsrc[n];
            float4 v = ((const float4*)x)[j];
            uint2 u;
            u.x = pack_bf16x2(v.x * sc, v.y * sc);
            u.y = pack_bf16x2(v.z * sc, v.w * sc);
            ((uint2*)g_xh)[j] = u;
        }
    }
}

// ---------------- kernel 4 (PROFILED): fused SpMM1 + GEMM1 ----------------
// block = 64 rows: gather g_xh -> smem tf32 A tile -> tf32 MMA -> bf16 g_xh2
__global__ void __launch_bounds__(256) k_fused1(const float* __restrict__ b, int N) {
    extern __shared__ unsigned smem[];
    unsigned* sA = smem;               // 64 x SA_ST (tf32 bits, pre-scaled by ndst)
    unsigned* sW = smem + 64 * SA_ST;  // 128 x SW_ST (tf32 bits)

    int t = threadIdx.x;
    int row0 = blockIdx.x * 64;
    int wid = t >> 5;
    int lane = t & 31;

    // stage pre-converted W1 (tf32)
#pragma unroll
    for (int i = 0; i < 16; i++) {
        int f = t + i * 256;
        int r = f >> 5;
        int c = f & 31;
        uint4 v = *(const uint4*)(g_w1t + r * 128 + c * 4);
        *(uint4*)(sW + r * SW_ST + c * 4) = v;
    }

    // gather phase: warp wid owns rows row0+wid*8 .. +7
    const uint2* xh = (const uint2*)g_xh;
#pragma unroll 1
    for (int q = 0; q < 8; q++) {
        int row = row0 + wid * 8 + q;
        float4 acc = make_float4(0.f, 0.f, 0.f, 0.f);
        if (row < N) {
            int e0 = g_off[row];
            int e1 = e0 + g_deg[NN + row];
            for (int base = e0; base < e1; base += 32) {
                int nrem = e1 - base;
                int idx = (lane < nrem) ? g_sorted[base + lane] : 0;
                int m = min(32, nrem);
                int j = 0;
                for (; j + 8 <= m; j += 8) {
                    uint2 u[8];
#pragma unroll
                    for (int p = 0; p < 8; p++) {
                        int s = __shfl_sync(0xffffffffu, idx, j + p);
                        u[p] = xh[(size_t)s * 32 + lane];
                    }
#pragma unroll
                    for (int p = 0; p < 8; p++) acc_bf16(acc, u[p]);
                }
                for (; j < m; j++) {
                    int s = __shfl_sync(0xffffffffu, idx, j);
                    acc_bf16(acc, xh[(size_t)s * 32 + lane]);
                }
            }
            float nd = g_ndst[row];
            acc.x *= nd; acc.y *= nd; acc.z *= nd; acc.w *= nd;
        }
        uint4 o;
        o.x = f2tf32(acc.x); o.y = f2tf32(acc.y);
        o.z = f2tf32(acc.z); o.w = f2tf32(acc.w);
        *(uint4*)(sA + (wid * 8 + q) * SA_ST + lane * 4) = o;
    }
    __syncthreads();

    // mma phase
    int g = lane >> 2;
    int tg = lane & 3;
    int wm = wid >> 2;
    int wn = wid & 3;

    float acc[2][4][4];
#pragma unroll
    for (int i = 0; i < 2; i++)
#pragma unroll
        for (int j = 0; j < 4; j++)
#pragma unroll
            for (int q = 0; q < 4; q++) acc[i][j][q] = 0.f;

    const unsigned* pA = sA + (wm * 32 + g) * SA_ST + tg;
    const unsigned* pB = sW + tg * SW_ST + wn * 32 + g;

#pragma unroll
    for (int ks = 0; ks < 16; ks++) {
        int k0 = ks * 8;
        unsigned a[2][4];
#pragma unroll
        for (int i = 0; i < 2; i++) {
            const unsigned* p = pA + i * 16 * SA_ST + k0;
            a[i][0] = p[0];
            a[i][1] = p[8 * SA_ST];
            a[i][2] = p[4];
            a[i][3] = p[8 * SA_ST + 4];
        }
        unsigned bb[4][2];
#pragma unroll
        for (int j = 0; j < 4; j++) {
            const unsigned* p = pB + k0 * SW_ST + j * 8;
            bb[j][0] = p[0];
            bb[j][1] = p[4 * SW_ST];
        }
#pragma unroll
        for (int i = 0; i < 2; i++)
#pragma unroll
            for (int j = 0; j < 4; j++)
                mma_tf32(acc[i][j][0], acc[i][j][1], acc[i][j][2], acc[i][j][3],
                         a[i][0], a[i][1], a[i][2], a[i][3], bb[j][0], bb[j][1]);
    }

    // epilogue: +bias, relu, *nsrc, bf16 pack -> g_xh2 (separate buffer: no race)
#pragma unroll
    for (int i = 0; i < 2; i++) {
        int rA = row0 + wm * 32 + i * 16 + g;
        int rB = rA + 8;
        float sA_ = (rA < N) ? g_nsrc[rA] : 0.f;
        float sB_ = (rB < N) ? g_nsrc[rB] : 0.f;
#pragma unroll
        for (int j = 0; j < 4; j++) {
            int c = wn * 32 + j * 8 + tg * 2;
            float bx = b[c], by = b[c + 1];
            if (rA < N) {
                float x0 = fmaxf(acc[i][j][0] + bx, 0.f) * sA_;
                float x1 = fmaxf(acc[i][j][1] + by, 0.f) * sA_;
                g_xh2[(size_t)rA * 64 + (c >> 1)] = pack_bf16x2(x0, x1);
            }
            if (rB < N) {
                float x2 = fmaxf(acc[i][j][2] + bx, 0.f) * sB_;
                float x3 = fmaxf(acc[i][j][3] + by, 0.f) * sB_;
                g_xh2[(size_t)rB * 64 + (c >> 1)] = pack_bf16x2(x2, x3);
            }
        }
    }
}

// ---------------- gemm2: pool partials = w_chunk^T @ xh2_chunk ----------------
__global__ void __launch_bounds__(256) k_gemm2(int N) {
    __shared__ unsigned sxh[8 * 64];
    __shared__ float sw[8 * 64];
    int t = threadIdx.x;
    int chunk = (N + NPART - 1) / NPART;
    int nb0 = blockIdx.x * chunk;
    int nend = min(nb0 + chunk, N);

    int dgrp = t & 31;
    int ggrp = t >> 5;

    float acc[8][4];
#pragma unroll
    for (int j = 0; j < 8; j++)
#pragma unroll
        for (int q = 0; q < 4; q++) acc[j][q] = 0.f;

    for (int nb = nb0; nb < nend; nb += 8) {
#pragma unroll
        for (int i = 0; i < 2; i++) {
            int word = t + i * 256;
            int s = word >> 6, p = word & 63;
            int n = nb + s;
            sxh[word] = (n < nend) ? g_xh2[(size_t)n * 64 + p] : 0u;
        }
#pragma unroll
        for (int i = 0; i < 2; i++) {
            int word = t + i * 256;
            int s = word >> 6, gg = word & 63;
            int n = nb + s;
            sw[word] = (n < nend) ? g_w[(size_t)n * 64 + gg] : 0.f;
        }
        __syncthreads();
#pragma unroll
        for (int s = 0; s < 8; s++) {
            uint2 xp = *(uint2*)&sxh[s * 64 + dgrp * 2];
            float x0 = bf_lo(xp.x), x1 = bf_hi(xp.x);
            float x2 = bf_lo(xp.y), x3 = bf_hi(xp.y);
#pragma unroll
            for (int j = 0; j < 8; j++) {
                float wv = sw[s * 64 + ggrp * 8 + j];
                acc[j][0] += wv * x0;
                acc[j][1] += wv * x1;
                acc[j][2] += wv * x2;
                acc[j][3] += wv * x3;
            }
        }
        __syncthreads();
    }

    float* pp = g_pp[blockIdx.x];
#pragma unroll
    for (int j = 0; j < 8; j++)
#pragma unroll
        for (int q = 0; q < 4; q++)
            pp[(ggrp * 8 + j) * DD + dgrp * 4 + q] = acc[j][q];
}

// ---------------- final: out = (Σ_p pp / cnt) @ W2 + b2 ----------------
__global__ void k_final(const float* __restrict__ W2, const float* __restrict__ b2,
                        float* __restrict__ out) {
    __shared__ float srow[DD];
    int g = blockIdx.x, t = threadIdx.x;
    float s = 0.f;
#pragma unroll 4
    for (int p = 0; p < NPART; p++) s += g_pp[p][g * DD + t];
    srow[t] = s / fmaxf(g_cnt[g], 1.f);
    __syncthreads();
    float a = b2[t];
#pragma unroll 8
    for (int k = 0; k < DD; k++) a += srow[k] * W2[k * DD + t];
    out[g * DD + t] = a;
}

// ---------------- launch ----------------
extern "C" void kernel_launch(void* const* d_in, const int* in_sizes, int n_in,
                              void* d_out, int out_size) {
    const float* in_feat = (const float*)d_in[0];
    const float* W1 = (const float*)d_in[1];
    const float* b1 = (const float*)d_in[2];
    const float* W2 = (const float*)d_in[3];
    const float* b2 = (const float*)d_in[4];
    const int* src = (const int*)d_in[5];
    const int* dst = (const int*)d_in[6];
    const int* gid = (const int*)d_in[7];
    int N = in_sizes[0] / DD;
    int E = in_sizes[5];
    (void)n_in; (void)out_size;

    void* p_deg;
    cudaGetSymbolAddress(&p_deg, g_deg);

    const int fused_smem = (64 * SA_ST + 128 * SW_ST) * (int)sizeof(unsigned);
    static int smem_set = 0;
    if (!smem_set) {
        cudaFuncSetAttribute(k_fused1, cudaFuncAttributeMaxDynamicSharedMemorySize, fused_smem);
        smem_set = 1;
    }

    cudaMemsetAsync(p_deg, 0, 2 * NN * sizeof(int));

    k_degree<<<1024, 256>>>(src, dst, E);                                     // 1
    k_nodeprep<<<(N + 255) / 256, 256>>>(gid, W1, N);                         // 2
    k_edge_node<<<(E + N * 32 + 255) / 256, 256>>>(src, dst, in_feat, E, N);  // 3
    k_fused1<<<(N + 63) / 64, 256, fused_smem>>>(b1, N);                      // 4 <- profiled
    k_gemm2<<<NPART, 256>>>(N);                                               // 5
    k_final<<<GG, DD>>>(W2, b2, (float*)d_out);                               // 6
}

// round 11
// speedup vs baseline: 1.0839x; 1.0839x over previous
#include <cuda_runtime.h>
#include <cuda_bf16.h>
#include <cstdint>

#define NN 100000
#define EE 1600000
#define DD 128
#define GG 64
#define NPART 296

#define SA_ST 132
#define SW_ST 136

// ---------------- device scratch ----------------
__device__ float    g_agg[(size_t)NN * DD];      // spmm1 output (fp32)
__device__ unsigned g_xh[(size_t)NN * DD / 2];   // bf16x2 scaled input features
__device__ unsigned g_xh2[(size_t)NN * DD / 2];  // bf16x2 layer-1 output
__device__ float    g_w[(size_t)NN * GG];        // per-(src,graph) pooling weights
__device__ unsigned g_w1t[DD * DD];              // W1 pre-converted to tf32
__device__ float    g_pp[NPART][GG * DD];        // gemm2 partial sums
__device__ uint2    g_gd[NN];                    // packed {gid, ndst}
__device__ int      g_deg[2 * NN];               // [0,NN)=deg_out, [NN,2NN)=deg_in
__device__ float    g_nsrc[NN];
__device__ float    g_ndst[NN];
__device__ float    g_cnt[GG];
__device__ int      g_off[NN];
__device__ int      g_cursor[NN];
__device__ int      g_sorted[EE];
__device__ int      g_counter;

// ---------------- helpers ----------------
__device__ __forceinline__ unsigned f2tf32(float x) {
    unsigned r;
    asm("cvt.rna.tf32.f32 %0, %1;" : "=r"(r) : "f"(x));
    return r;
}
__device__ __forceinline__ unsigned pack_bf16x2(float lo, float hi) {
    unsigned r;
    asm("cvt.rn.bf16x2.f32 %0, %1, %2;" : "=r"(r) : "f"(hi), "f"(lo));
    return r;
}
__device__ __forceinline__ void mma_tf32(float& d0, float& d1, float& d2, float& d3,
                                         unsigned a0, unsigned a1, unsigned a2, unsigned a3,
                                         unsigned b0, unsigned b1) {
    asm("mma.sync.aligned.m16n8k8.row.col.f32.tf32.tf32.f32 "
        "{%0,%1,%2,%3}, {%4,%5,%6,%7}, {%8,%9}, {%0,%1,%2,%3};"
        : "+f"(d0), "+f"(d1), "+f"(d2), "+f"(d3)
        : "r"(a0), "r"(a1), "r"(a2), "r"(a3), "r"(b0), "r"(b1));
}
__device__ __forceinline__ float bf_lo(unsigned u) { return __uint_as_float(u << 16); }
__device__ __forceinline__ float bf_hi(unsigned u) { return __uint_as_float(u & 0xffff0000u); }
__device__ __forceinline__ void acc_bf16(float4& a, uint2 u) {
    a.x += bf_lo(u.x); a.y += bf_hi(u.x);
    a.z += bf_lo(u.y); a.w += bf_hi(u.y);
}

// ---------------- kernel 1: degree count (int4 edge loads) + zero w/cnt/counter ----------------
__global__ void k_degree(const int* __restrict__ src, const int* __restrict__ dst, int E) {
    int i0 = blockIdx.x * blockDim.x + threadIdx.x;
    int stride = gridDim.x * blockDim.x;
    float4 z = make_float4(0.f, 0.f, 0.f, 0.f);
    for (int i = i0; i < NN * GG / 4; i += stride) ((float4*)g_w)[i] = z;
    if (i0 < GG) g_cnt[i0] = 0.f;
    if (i0 == GG) g_counter = 0;
    int E4 = E >> 2;
    const int4* src4 = (const int4*)src;
    const int4* dst4 = (const int4*)dst;
    for (int i = i0; i < E4; i += stride) {
        int4 s = src4[i];
        int4 d = dst4[i];
        atomicAdd(&g_deg[s.x], 1); atomicAdd(&g_deg[s.y], 1);
        atomicAdd(&g_deg[s.z], 1); atomicAdd(&g_deg[s.w], 1);
        atomicAdd(&g_deg[NN + d.x], 1); atomicAdd(&g_deg[NN + d.y], 1);
        atomicAdd(&g_deg[NN + d.z], 1); atomicAdd(&g_deg[NN + d.w], 1);
    }
    for (int i = E4 * 4 + i0; i < E; i += stride) {
        atomicAdd(&g_deg[src[i]], 1);
        atomicAdd(&g_deg[NN + dst[i]], 1);
    }
}

// ---------------- kernel 2: norms, gd pack, counts, offsets ----------------
__global__ void k_nodeprep(const int* __restrict__ gid, int N) {
    int i = blockIdx.x * blockDim.x + threadIdx.x;
    if (i < N) {
        int dout = g_deg[i];
        int din = g_deg[NN + i];
        float ns = rsqrtf((float)max(dout, 1));
        float nd = rsqrtf((float)max(din, 1));
        g_nsrc[i] = ns;
        g_ndst[i] = nd;
        int g = gid[i];
        g_gd[i] = make_uint2((unsigned)g, __float_as_uint(nd));
        atomicAdd(&g_cnt[g], 1.f);
        int off = atomicAdd(&g_counter, din);   // arbitrary-order segment assignment
        g_off[i] = off;
        g_cursor[i] = off;
    }
}

// ---------------- kernel 3 (tiny): W1 -> tf32 ----------------
__global__ void k_w1conv(const float* __restrict__ W1) {
    int i = blockIdx.x * blockDim.x + threadIdx.x;
    if (i < DD * DD) g_w1t[i] = f2tf32(W1[i]);
}

// ---------------- kernel 4 (PROFILED): scatter + wbuild (edges) and bf16 prep (nodes) ----------------
__global__ void k_edge_node(const int* __restrict__ src, const int* __restrict__ dst,
                            const float* __restrict__ x, int E, int N) {
    int i = blockIdx.x * blockDim.x + threadIdx.x;
    if (i < E) {
        int s = src[i];
        int d = dst[i];
        int p = atomicAdd(&g_cursor[d], 1);
        g_sorted[p] = s;
        uint2 gd = g_gd[d];
        atomicAdd(&g_w[(size_t)s * GG + gd.x], __uint_as_float(gd.y));
    } else {
        int j = i - E;                       // float4 index over node features
        if (j < N * 32) {
            int n = j >> 5;
            float sc = g_nsrc[n];
            float4 v = ((const float4*)x)[j];
            uint2 u;
            u.x = pack_bf16x2(v.x * sc, v.y * sc);
            u.y = pack_bf16x2(v.z * sc, v.w * sc);
            ((uint2*)g_xh)[j] = u;
        }
    }
}

// ---------------- kernel 5: SpMM layer 1 (unfused, known 54us) ----------------
__global__ void __launch_bounds__(256) k_spmm1(int N) {
    int warp = (blockIdx.x * blockDim.x + threadIdx.x) >> 5;
    if (warp >= N) return;
    int lane = threadIdx.x & 31;
    const uint2* xh = (const uint2*)g_xh;
    int e0 = g_off[warp];
    int e1 = e0 + g_deg[NN + warp];
    float4 acc = make_float4(0.f, 0.f, 0.f, 0.f);
    for (int base = e0; base < e1; base += 32) {
        int nrem = e1 - base;
        int idx = (lane < nrem) ? g_sorted[base + lane] : 0;
        int m = min(32, nrem);
        int j = 0;
        for (; j + 8 <= m; j += 8) {
            uint2 u[8];
#pragma unroll
            for (int q = 0; q < 8; q++) {
                int s = __shfl_sync(0xffffffffu, idx, j + q);
                u[q] = xh[(size_t)s * 32 + lane];
            }
#pragma unroll
            for (int q = 0; q < 8; q++) acc_bf16(acc, u[q]);
        }
        for (; j < m; j++) {
            int s = __shfl_sync(0xffffffffu, idx, j);
            acc_bf16(acc, xh[(size_t)s * 32 + lane]);
        }
    }
    *(float4*)(g_agg + (size_t)warp * DD + lane * 4) = acc;
}

// ---------------- kernel 6: dense stage 1 (tf32 MMA, no inner-loop cvt) ----------------
__global__ void __launch_bounds__(256) k_gemm1(const float* __restrict__ b, int N) {
    extern __shared__ unsigned smem[];
    unsigned* sA = smem;               // 64 x SA_ST tf32
    unsigned* sW = smem + 64 * SA_ST;  // 128 x SW_ST tf32

    int t = threadIdx.x;
    int row0 = blockIdx.x * 64;
    int wid = t >> 5;
    int lane = t & 31;

    // stage pre-converted W1
#pragma unroll
    for (int i = 0; i < 16; i++) {
        int f = t + i * 256;
        int r = f >> 5;
        int c = f & 31;
        uint4 v = *(const uint4*)(g_w1t + r * 128 + c * 4);
        *(uint4*)(sW + r * SW_ST + c * 4) = v;
    }
    // stage A: g_agg * ndst -> tf32
#pragma unroll
    for (int i = 0; i < 8; i++) {
        int f = t + i * 256;
        int r = f >> 5;
        int c = f & 31;
        int row = row0 + r;
        uint4 o = make_uint4(0u, 0u, 0u, 0u);
        if (row < N) {
            float4 v = *(const float4*)(g_agg + (size_t)row * DD + c * 4);
            float s = g_ndst[row];
            o.x = f2tf32(v.x * s); o.y = f2tf32(v.y * s);
            o.z = f2tf32(v.z * s); o.w = f2tf32(v.w * s);
        }
        *(uint4*)(sA + r * SA_ST + c * 4) = o;
    }
    __syncthreads();

    int g = lane >> 2;
    int tg = lane & 3;
    int wm = wid >> 2;
    int wn = wid & 3;

    float acc[2][4][4];
#pragma unroll
    for (int i = 0; i < 2; i++)
#pragma unroll
        for (int j = 0; j < 4; j++)
#pragma unroll
            for (int q = 0; q < 4; q++) acc[i][j][q] = 0.f;

    const unsigned* pA = sA + (wm * 32 + g) * SA_ST + tg;
    const unsigned* pB = sW + tg * SW_ST + wn * 32 + g;

#pragma unroll
    for (int ks = 0; ks < 16; ks++) {
        int k0 = ks * 8;
        unsigned a[2][4];
#pragma unroll
        for (int i = 0; i < 2; i++) {
            const unsigned* p = pA + i * 16 * SA_ST + k0;
            a[i][0] = p[0];
            a[i][1] = p[8 * SA_ST];
            a[i][2] = p[4];
            a[i][3] = p[8 * SA_ST + 4];
        }
        unsigned bb[4][2];
#pragma unroll
        for (int j = 0; j < 4; j++) {
            const unsigned* p = pB + k0 * SW_ST + j * 8;
            bb[j][0] = p[0];
            bb[j][1] = p[4 * SW_ST];
        }
#pragma unroll
        for (int i = 0; i < 2; i++)
#pragma unroll
            for (int j = 0; j < 4; j++)
                mma_tf32(acc[i][j][0], acc[i][j][1], acc[i][j][2], acc[i][j][3],
                         a[i][0], a[i][1], a[i][2], a[i][3], bb[j][0], bb[j][1]);
    }

    // epilogue: +bias, relu, *nsrc, bf16 pack -> g_xh2
#pragma unroll
    for (int i = 0; i < 2; i++) {
        int rA = row0 + wm * 32 + i * 16 + g;
        int rB = rA + 8;
        float sA_ = (rA < N) ? g_nsrc[rA] : 0.f;
        float sB_ = (rB < N) ? g_nsrc[rB] : 0.f;
#pragma unroll
        for (int j = 0; j < 4; j++) {
            int c = wn * 32 + j * 8 + tg * 2;
            float bx = b[c], by = b[c + 1];
            if (rA < N) {
                float x0 = fmaxf(acc[i][j][0] + bx, 0.f) * sA_;
                float x1 = fmaxf(acc[i][j][1] + by, 0.f) * sA_;
                g_xh2[(size_t)rA * 64 + (c >> 1)] = pack_bf16x2(x0, x1);
            }
            if (rB < N) {
                float x2 = fmaxf(acc[i][j][2] + bx, 0.f) * sB_;
                float x3 = fmaxf(acc[i][j][3] + by, 0.f) * sB_;
                g_xh2[(size_t)rB * 64 + (c >> 1)] = pack_bf16x2(x2, x3);
            }
        }
    }
}

// ---------------- kernel 7: gemm2 pool partials = w_chunk^T @ xh2_chunk ----------------
__global__ void __launch_bounds__(256) k_gemm2(int N) {
    __shared__ unsigned sxh[8 * 64];
    __shared__ float sw[8 * 64];
    int t = threadIdx.x;
    int chunk = (N + NPART - 1) / NPART;
    int nb0 = blockIdx.x * chunk;
    int nend = min(nb0 + chunk, N);

    int dgrp = t & 31;
    int ggrp = t >> 5;

    float acc[8][4];
#pragma unroll
    for (int j = 0; j < 8; j++)
#pragma unroll
        for (int q = 0; q < 4; q++) acc[j][q] = 0.f;

    for (int nb = nb0; nb < nend; nb += 8) {
#pragma unroll
        for (int i = 0; i < 2; i++) {
            int word = t + i * 256;
            int s = word >> 6, p = word & 63;
            int n = nb + s;
            sxh[word] = (n < nend) ? g_xh2[(size_t)n * 64 + p] : 0u;
        }
#pragma unroll
        for (int i = 0; i < 2; i++) {
            int word = t + i * 256;
            int s = word >> 6, gg = word & 63;
            int n = nb + s;
            sw[word] = (n < nend) ? g_w[(size_t)n * 64 + gg] : 0.f;
        }
        __syncthreads();
#pragma unroll
        for (int s = 0; s < 8; s++) {
            uint2 xp = *(uint2*)&sxh[s * 64 + dgrp * 2];
            float x0 = bf_lo(xp.x), x1 = bf_hi(xp.x);
            float x2 = bf_lo(xp.y), x3 = bf_hi(xp.y);
#pragma unroll
            for (int j = 0; j < 8; j++) {
                float wv = sw[s * 64 + ggrp * 8 + j];
                acc[j][0] += wv * x0;
                acc[j][1] += wv * x1;
                acc[j][2] += wv * x2;
                acc[j][3] += wv * x3;
            }
        }
        __syncthreads();
    }

    float* pp = g_pp[blockIdx.x];
#pragma unroll
    for (int j = 0; j < 8; j++)
#pragma unroll
        for (int q = 0; q < 4; q++)
            pp[(ggrp * 8 + j) * DD + dgrp * 4 + q] = acc[j][q];
}

// ---------------- kernel 8: out = (Σ_p pp / cnt) @ W2 + b2 ----------------
__global__ void k_final(const float* __restrict__ W2, const float* __restrict__ b2,
                        float* __restrict__ out) {
    __shared__ float srow[DD];
    int g = blockIdx.x, t = threadIdx.x;
    float s = 0.f;
#pragma unroll 4
    for (int p = 0; p < NPART; p++) s += g_pp[p][g * DD + t];
    srow[t] = s / fmaxf(g_cnt[g], 1.f);
    __syncthreads();
    float a = b2[t];
#pragma unroll 8
    for (int k = 0; k < DD; k++) a += srow[k] * W2[k * DD + t];
    out[g * DD + t] = a;
}

// ---------------- launch ----------------
extern "C" void kernel_launch(void* const* d_in, const int* in_sizes, int n_in,
                              void* d_out, int out_size) {
    const float* in_feat = (const float*)d_in[0];
    const float* W1 = (const float*)d_in[1];
    const float* b1 = (const float*)d_in[2];
    const float* W2 = (const float*)d_in[3];
    const float* b2 = (const float*)d_in[4];
    const int* src = (const int*)d_in[5];
    const int* dst = (const int*)d_in[6];
    const int* gid = (const int*)d_in[7];
    int N = in_sizes[0] / DD;
    int E = in_sizes[5];
    (void)n_in; (void)out_size;

    void* p_deg;
    cudaGetSymbolAddress(&p_deg, g_deg);

    const int gemm_smem = (64 * SA_ST + 128 * SW_ST) * (int)sizeof(unsigned);
    static int smem_set = 0;
    if (!smem_set) {
        cudaFuncSetAttribute(k_gemm1, cudaFuncAttributeMaxDynamicSharedMemorySize, gemm_smem);
        smem_set = 1;
    }

    cudaMemsetAsync(p_deg, 0, 2 * NN * sizeof(int));

    k_degree<<<1024, 256>>>(src, dst, E);                                     // 1
    k_nodeprep<<<(N + 255) / 256, 256>>>(gid, N);                             // 2
    k_w1conv<<<(DD * DD + 255) / 256, 256>>>(W1);                             // 3 (tiny)
    k_edge_node<<<(E + N * 32 + 255) / 256, 256>>>(src, dst, in_feat, E, N);  // 4 <- profiled
    k_spmm1<<<(N + 7) / 8, 256>>>(N);                                         // 5
    k_gemm1<<<(N + 63) / 64, 256, gemm_smem>>>(b1, N);                        // 6
    k_gemm2<<<NPART, 256>>>(N);                                               // 7
    k_final<<<GG, DD>>>(W2, b2, (float*)d_out);                               // 8
}

// round 12
// speedup vs baseline: 1.1094x; 1.0235x over previous
#include <cuda_runtime.h>
#include <cuda_bf16.h>
#include <cstdint>

#define NN 100000
#define EE 1600000
#define DD 128
#define GG 64
#define NB2 148          // gemm2 blocks

#define SA_ST 132
#define SW_ST 136
#define ST_W 65
#define ST_X 66

// ---------------- device scratch ----------------
__device__ float    g_agg[(size_t)NN * DD];      // spmm1 output (fp32)
__device__ unsigned g_xh[(size_t)NN * DD / 2];   // bf16x2 scaled input features
__device__ unsigned g_xh2[(size_t)NN * DD / 2];  // bf16x2 layer-1 output
__device__ float    g_w[(size_t)NN * GG];        // per-(src,graph) pooling weights
__device__ unsigned g_w1t[DD * DD];              // W1 pre-converted to tf32
__device__ float    g_pool[GG * DD];             // pooled sums (red target)
__device__ uint2    g_gd[NN];                    // packed {gid, ndst}
__device__ int      g_deg[2 * NN];               // [0,NN)=deg_out, [NN,2NN)=deg_in
__device__ float    g_nsrc[NN];
__device__ float    g_ndst[NN];
__device__ float    g_cnt[GG];
__device__ int      g_off[NN];
__device__ int      g_cursor[NN];
__device__ int      g_sorted[EE];
__device__ int      g_counter;

// ---------------- helpers ----------------
__device__ __forceinline__ unsigned f2tf32(float x) {
    unsigned r;
    asm("cvt.rna.tf32.f32 %0, %1;" : "=r"(r) : "f"(x));
    return r;
}
__device__ __forceinline__ unsigned pack_bf16x2(float lo, float hi) {
    unsigned r;
    asm("cvt.rn.bf16x2.f32 %0, %1, %2;" : "=r"(r) : "f"(hi), "f"(lo));
    return r;
}
__device__ __forceinline__ void mma_tf32(float& d0, float& d1, float& d2, float& d3,
                                         unsigned a0, unsigned a1, unsigned a2, unsigned a3,
                                         unsigned b0, unsigned b1) {
    asm("mma.sync.aligned.m16n8k8.row.col.f32.tf32.tf32.f32 "
        "{%0,%1,%2,%3}, {%4,%5,%6,%7}, {%8,%9}, {%0,%1,%2,%3};"
        : "+f"(d0), "+f"(d1), "+f"(d2), "+f"(d3)
        : "r"(a0), "r"(a1), "r"(a2), "r"(a3), "r"(b0), "r"(b1));
}
__device__ __forceinline__ float bf_lo(unsigned u) { return __uint_as_float(u << 16); }
__device__ __forceinline__ float bf_hi(unsigned u) { return __uint_as_float(u & 0xffff0000u); }
__device__ __forceinline__ void acc_bf16(float4& a, uint2 u) {
    a.x += bf_lo(u.x); a.y += bf_hi(u.x);
    a.z += bf_lo(u.y); a.w += bf_hi(u.y);
}
__device__ __forceinline__ void red_v4(float* p, float4 v) {
    asm volatile("red.global.add.v4.f32 [%0], {%1,%2,%3,%4};"
                 :: "l"(p), "f"(v.x), "f"(v.y), "f"(v.z), "f"(v.w) : "memory");
}

// ---------------- launch 1 (tiny): W1 -> tf32 ----------------
__global__ void k_w1conv(const float* __restrict__ W1) {
    int i = blockIdx.x * blockDim.x + threadIdx.x;
    if (i < DD * DD) g_w1t[i] = f2tf32(W1[i]);
}

// ---------------- launch 2: zero g_w ----------------
__global__ void k_zero_w() {
    int i0 = blockIdx.x * blockDim.x + threadIdx.x;
    int stride = gridDim.x * blockDim.x;
    float4 z = make_float4(0.f, 0.f, 0.f, 0.f);
    for (int i = i0; i < NN * GG / 4; i += stride) ((float4*)g_w)[i] = z;
}

// ---------------- launch 3: zero deg/pool/cnt/counter ----------------
__global__ void k_zero_misc() {
    int i0 = blockIdx.x * blockDim.x + threadIdx.x;
    int stride = gridDim.x * blockDim.x;
    for (int i = i0; i < 2 * NN; i += stride) g_deg[i] = 0;
    for (int i = i0; i < GG * DD; i += stride) g_pool[i] = 0.f;
    if (i0 < GG) g_cnt[i0] = 0.f;
    if (i0 == GG) g_counter = 0;
}

// ---------------- launch 4 (PROFILED): degree count (scalar, R5 form) ----------------
__global__ void k_degree(const int* __restrict__ src, const int* __restrict__ dst, int E) {
    int i = blockIdx.x * blockDim.x + threadIdx.x;
    int stride = gridDim.x * blockDim.x;
    for (; i < E; i += stride) {
        atomicAdd(&g_deg[src[i]], 1);
        atomicAdd(&g_deg[NN + dst[i]], 1);
    }
}

// ---------------- launch 5: norms, gd pack, counts, offsets ----------------
__global__ void k_nodeprep(const int* __restrict__ gid, int N) {
    int i = blockIdx.x * blockDim.x + threadIdx.x;
    if (i < N) {
        int dout = g_deg[i];
        int din = g_deg[NN + i];
        float ns = rsqrtf((float)max(dout, 1));
        float nd = rsqrtf((float)max(din, 1));
        g_nsrc[i] = ns;
        g_ndst[i] = nd;
        int g = gid[i];
        g_gd[i] = make_uint2((unsigned)g, __float_as_uint(nd));
        atomicAdd(&g_cnt[g], 1.f);
        int off = atomicAdd(&g_counter, din);   // arbitrary-order segment assignment
        g_off[i] = off;
        g_cursor[i] = off;
    }
}

// ---------------- launch 6: scatter + wbuild (edges) and bf16 prep (nodes) ----------------
__global__ void k_edge_node(const int* __restrict__ src, const int* __restrict__ dst,
                            const float* __restrict__ x, int E, int N) {
    int i = blockIdx.x * blockDim.x + threadIdx.x;
    if (i < E) {
        int s = src[i];
        int d = dst[i];
        int p = atomicAdd(&g_cursor[d], 1);
        g_sorted[p] = s;
        uint2 gd = g_gd[d];
        atomicAdd(&g_w[(size_t)s * GG + gd.x], __uint_as_float(gd.y));
    } else {
        int j = i - E;                       // float4 index over node features
        if (j < N * 32) {
            int n = j >> 5;
            float sc = g_nsrc[n];
            float4 v = ((const float4*)x)[j];
            uint2 u;
            u.x = pack_bf16x2(v.x * sc, v.y * sc);
            u.y = pack_bf16x2(v.z * sc, v.w * sc);
            ((uint2*)g_xh)[j] = u;
        }
    }
}

// ---------------- launch 7: SpMM layer 1 ----------------
__global__ void __launch_bounds__(256) k_spmm1(int N) {
    int warp = (blockIdx.x * blockDim.x + threadIdx.x) >> 5;
    if (warp >= N) return;
    int lane = threadIdx.x & 31;
    const uint2* xh = (const uint2*)g_xh;
    int e0 = g_off[warp];
    int e1 = e0 + g_deg[NN + warp];
    float4 acc = make_float4(0.f, 0.f, 0.f, 0.f);
    for (int base = e0; base < e1; base += 32) {
        int nrem = e1 - base;
        int idx = (lane < nrem) ? g_sorted[base + lane] : 0;
        int m = min(32, nrem);
        int j = 0;
        for (; j + 8 <= m; j += 8) {
            uint2 u[8];
#pragma unroll
            for (int q = 0; q < 8; q++) {
                int s = __shfl_sync(0xffffffffu, idx, j + q);
                u[q] = xh[(size_t)s * 32 + lane];
            }
#pragma unroll
            for (int q = 0; q < 8; q++) acc_bf16(acc, u[q]);
        }
        for (; j < m; j++) {
            int s = __shfl_sync(0xffffffffu, idx, j);
            acc_bf16(acc, xh[(size_t)s * 32 + lane]);
        }
    }
    *(float4*)(g_agg + (size_t)warp * DD + lane * 4) = acc;
}

// ---------------- launch 8: dense stage 1 (tf32 MMA, no inner-loop cvt) ----------------
__global__ void __launch_bounds__(256) k_gemm1(const float* __restrict__ b, int N) {
    extern __shared__ unsigned smem[];
    unsigned* sA = smem;               // 64 x SA_ST tf32
    unsigned* sW = smem + 64 * SA_ST;  // 128 x SW_ST tf32

    int t = threadIdx.x;
    int row0 = blockIdx.x * 64;
    int wid = t >> 5;
    int lane = t & 31;

#pragma unroll
    for (int i = 0; i < 16; i++) {
        int f = t + i * 256;
        int r = f >> 5;
        int c = f & 31;
        uint4 v = *(const uint4*)(g_w1t + r * 128 + c * 4);
        *(uint4*)(sW + r * SW_ST + c * 4) = v;
    }
#pragma unroll
    for (int i = 0; i < 8; i++) {
        int f = t + i * 256;
        int r = f >> 5;
        int c = f & 31;
        int row = row0 + r;
        uint4 o = make_uint4(0u, 0u, 0u, 0u);
        if (row < N) {
            float4 v = *(const float4*)(g_agg + (size_t)row * DD + c * 4);
            float s = g_ndst[row];
            o.x = f2tf32(v.x * s); o.y = f2tf32(v.y * s);
            o.z = f2tf32(v.z * s); o.w = f2tf32(v.w * s);
        }
        *(uint4*)(sA + r * SA_ST + c * 4) = o;
    }
    __syncthreads();

    int g = lane >> 2;
    int tg = lane & 3;
    int wm = wid >> 2;
    int wn = wid & 3;

    float acc[2][4][4];
#pragma unroll
    for (int i = 0; i < 2; i++)
#pragma unroll
        for (int j = 0; j < 4; j++)
#pragma unroll
            for (int q = 0; q < 4; q++) acc[i][j][q] = 0.f;

    const unsigned* pA = sA + (wm * 32 + g) * SA_ST + tg;
    const unsigned* pB = sW + tg * SW_ST + wn * 32 + g;

#pragma unroll
    for (int ks = 0; ks < 16; ks++) {
        int k0 = ks * 8;
        unsigned a[2][4];
#pragma unroll
        for (int i = 0; i < 2; i++) {
            const unsigned* p = pA + i * 16 * SA_ST + k0;
            a[i][0] = p[0];
            a[i][1] = p[8 * SA_ST];
            a[i][2] = p[4];
            a[i][3] = p[8 * SA_ST + 4];
        }
        unsigned bb[4][2];
#pragma unroll
        for (int j = 0; j < 4; j++) {
            const unsigned* p = pB + k0 * SW_ST + j * 8;
            bb[j][0] = p[0];
            bb[j][1] = p[4 * SW_ST];
        }
#pragma unroll
        for (int i = 0; i < 2; i++)
#pragma unroll
            for (int j = 0; j < 4; j++)
                mma_tf32(acc[i][j][0], acc[i][j][1], acc[i][j][2], acc[i][j][3],
                         a[i][0], a[i][1], a[i][2], a[i][3], bb[j][0], bb[j][1]);
    }

#pragma unroll
    for (int i = 0; i < 2; i++) {
        int rA = row0 + wm * 32 + i * 16 + g;
        int rB = rA + 8;
        float sA_ = (rA < N) ? g_nsrc[rA] : 0.f;
        float sB_ = (rB < N) ? g_nsrc[rB] : 0.f;
#pragma unroll
        for (int j = 0; j < 4; j++) {
            int c = wn * 32 + j * 8 + tg * 2;
            float bx = b[c], by = b[c + 1];
            if (rA < N) {
                float x0 = fmaxf(acc[i][j][0] + bx, 0.f) * sA_;
                float x1 = fmaxf(acc[i][j][1] + by, 0.f) * sA_;
                g_xh2[(size_t)rA * 64 + (c >> 1)] = pack_bf16x2(x0, x1);
            }
            if (rB < N) {
                float x2 = fmaxf(acc[i][j][2] + bx, 0.f) * sB_;
                float x3 = fmaxf(acc[i][j][3] + by, 0.f) * sB_;
                g_xh2[(size_t)rB * 64 + (c >> 1)] = pack_bf16x2(x2, x3);
            }
        }
    }
}

// ---------------- launch 9: gemm2 via tf32 MMA: g_pool += w_chunk^T @ xh2_chunk ----------------
// P[g (64) ][ d (128) ] = sum_n w[n][g] * xh2[n][d]
// 8 warps: wm = wid>>1 (m16 tile of G), wn = wid&1 (64 dims); per chunk K=8 nodes.
__global__ void __launch_bounds__(256) k_gemm2(int N) {
    __shared__ float    sw[8 * ST_W];      // w chunk  [k][g]
    __shared__ unsigned sx[8 * ST_X];      // xh2 chunk [k][word]
    __shared__ float    spool[GG * DD];    // 32KB output staging

    int t = threadIdx.x;
    int wid = t >> 5;
    int lane = t & 31;
    int g = lane >> 2;
    int tg = lane & 3;
    int wm = wid >> 1;       // 0..3  -> m tile = wm*16
    int wn = wid & 1;        // 0..1  -> dims wn*64 ..

    int chunk = (N + NB2 - 1) / NB2;
    int nb0 = blockIdx.x * chunk;
    int nend = min(nb0 + chunk, N);

    float acc[8][4];
#pragma unroll
    for (int j = 0; j < 8; j++)
#pragma unroll
        for (int q = 0; q < 4; q++) acc[j][q] = 0.f;

    for (int nb = nb0; nb < nend; nb += 8) {
#pragma unroll
        for (int i = 0; i < 2; i++) {
            int word = t + i * 256;          // 0..511
            int k = word >> 6, gg = word & 63;
            int n = nb + k;
            bool ok = (n < nend);
            sw[k * ST_W + gg] = ok ? g_w[(size_t)n * GG + gg] : 0.f;
            sx[k * ST_X + gg] = ok ? g_xh2[(size_t)n * 64 + gg] : 0u;
        }
        __syncthreads();

        // A frag: A[m=graph][k], rows wm*16+g(+8), cols tg(+4)
        unsigned a0 = f2tf32(sw[tg * ST_W + wm * 16 + g]);
        unsigned a1 = f2tf32(sw[tg * ST_W + wm * 16 + g + 8]);
        unsigned a2 = f2tf32(sw[(tg + 4) * ST_W + wm * 16 + g]);
        unsigned a3 = f2tf32(sw[(tg + 4) * ST_W + wm * 16 + g + 8]);

#pragma unroll
        for (int j = 0; j < 8; j++) {
            int nj = wn * 64 + j * 8;            // dim base (multiple of 8)
            int wrd = (nj >> 1) + (g >> 1);      // bf16x2 word index
            unsigned u0 = sx[tg * ST_X + wrd];
            unsigned u1 = sx[(tg + 4) * ST_X + wrd];
            unsigned b0 = (g & 1) ? (u0 & 0xffff0000u) : (u0 << 16);
            unsigned b1 = (g & 1) ? (u1 & 0xffff0000u) : (u1 << 16);
            mma_tf32(acc[j][0], acc[j][1], acc[j][2], acc[j][3],
                     a0, a1, a2, a3, b0, b1);
        }
        __syncthreads();
    }

    // stage tile to smem, then vector-reduce to g_pool
#pragma unroll
    for (int j = 0; j < 8; j++) {
        int nj = wn * 64 + j * 8 + tg * 2;
        int r = wm * 16 + g;
        spool[r * DD + nj] = acc[j][0];
        spool[r * DD + nj + 1] = acc[j][1];
        spool[(r + 8) * DD + nj] = acc[j][2];
        spool[(r + 8) * DD + nj + 1] = acc[j][3];
    }
    __syncthreads();
#pragma unroll
    for (int i = 0; i < 8; i++) {
        int q = t + i * 256;                 // 0..2047 float4s
        float4 v = ((float4*)spool)[q];
        red_v4(g_pool + q * 4, v);
    }
}

// ---------------- launch 10: out = (g_pool/cnt) @ W2 + b2 ----------------
__global__ void k_final(const float* __restrict__ W2, const float* __restrict__ b2,
                        float* __restrict__ out) {
    __shared__ float srow[DD];
    int g = blockIdx.x, t = threadIdx.x;
    srow[t] = g_pool[g * DD + t] / fmaxf(g_cnt[g], 1.f);
    __syncthreads();
    float a = b2[t];
#pragma unroll 8
    for (int k = 0; k < DD; k++) a += srow[k] * W2[k * DD + t];
    out[g * DD + t] = a;
}

// ---------------- launch ----------------
extern "C" void kernel_launch(void* const* d_in, const int* in_sizes, int n_in,
                              void* d_out, int out_size) {
    const float* in_feat = (const float*)d_in[0];
    const float* W1 = (const float*)d_in[1];
    const float* b1 = (const float*)d_in[2];
    const float* W2 = (const float*)d_in[3];
    const float* b2 = (const float*)d_in[4];
    const int* src = (const int*)d_in[5];
    const int* dst = (const int*)d_in[6];
    const int* gid = (const int*)d_in[7];
    int N = in_sizes[0] / DD;
    int E = in_sizes[5];
    (void)n_in; (void)out_size;

    const int gemm_smem = (64 * SA_ST + 128 * SW_ST) * (int)sizeof(unsigned);
    static int smem_set = 0;
    if (!smem_set) {
        cudaFuncSetAttribute(k_gemm1, cudaFuncAttributeMaxDynamicSharedMemorySize, gemm_smem);
        smem_set = 1;
    }

    k_w1conv<<<(DD * DD + 255) / 256, 256>>>(W1);                             // 1 (tiny)
    k_zero_w<<<512, 256>>>();                                                 // 2
    k_zero_misc<<<512, 256>>>();                                              // 3
    k_degree<<<1024, 256>>>(src, dst, E);                                     // 4 <- profiled
    k_nodeprep<<<(N + 255) / 256, 256>>>(gid, N);                             // 5
    k_edge_node<<<(E + N * 32 + 255) / 256, 256>>>(src, dst, in_feat, E, N);  // 6
    k_spmm1<<<(N + 7) / 8, 256>>>(N);                                         // 7
    k_gemm1<<<(N + 63) / 64, 256, gemm_smem>>>(b1, N);                        // 8
    k_gemm2<<<NB2, 256>>>(N);                                                 // 9
    k_final<<<GG, DD>>>(W2, b2, (float*)d_out);                               // 10
}

// round 13
// speedup vs baseline: 1.1704x; 1.0550x over previous
#include <cuda_runtime.h>
#include <cuda_bf16.h>
#include <cstdint>

#define NN 100000
#define EE 1600000
#define DD 128
#define GG 64
#define NB2 148          // gemm2 blocks

#define SA_ST 132
#define SW_ST 136
#define ST_W 65
#define ST_X 66

// ---------------- device scratch ----------------
__device__ float    g_agg[(size_t)NN * DD];      // spmm1 output (fp32)
__device__ unsigned g_xh[(size_t)NN * DD / 2];   // bf16x2 scaled input features
__device__ unsigned g_xh2[(size_t)NN * DD / 2];  // bf16x2 layer-1 output
__device__ float    g_w[(size_t)NN * GG];        // per-(src,graph) pooling weights
__device__ unsigned g_w1t[DD * DD];              // W1 pre-converted to tf32
__device__ float    g_pool[GG * DD];             // pooled sums (red target)
__device__ uint2    g_gd[NN];                    // packed {gid, ndst}
__device__ int      g_deg[2 * NN];               // [0,NN)=deg_out, [NN,2NN)=deg_in
__device__ float    g_nsrc[NN];
__device__ float    g_ndst[NN];
__device__ float    g_cnt[GG];
__device__ int      g_off[NN];
__device__ int      g_cursor[NN];
__device__ int      g_sorted[EE];
__device__ int      g_counter;

// ---------------- helpers ----------------
__device__ __forceinline__ unsigned f2tf32(float x) {
    unsigned r;
    asm("cvt.rna.tf32.f32 %0, %1;" : "=r"(r) : "f"(x));
    return r;
}
__device__ __forceinline__ unsigned pack_bf16x2(float lo, float hi) {
    unsigned r;
    asm("cvt.rn.bf16x2.f32 %0, %1, %2;" : "=r"(r) : "f"(hi), "f"(lo));
    return r;
}
__device__ __forceinline__ void mma_tf32(float& d0, float& d1, float& d2, float& d3,
                                         unsigned a0, unsigned a1, unsigned a2, unsigned a3,
                                         unsigned b0, unsigned b1) {
    asm("mma.sync.aligned.m16n8k8.row.col.f32.tf32.tf32.f32 "
        "{%0,%1,%2,%3}, {%4,%5,%6,%7}, {%8,%9}, {%0,%1,%2,%3};"
        : "+f"(d0), "+f"(d1), "+f"(d2), "+f"(d3)
        : "r"(a0), "r"(a1), "r"(a2), "r"(a3), "r"(b0), "r"(b1));
}
__device__ __forceinline__ float bf_lo(unsigned u) { return __uint_as_float(u << 16); }
__device__ __forceinline__ float bf_hi(unsigned u) { return __uint_as_float(u & 0xffff0000u); }
__device__ __forceinline__ void acc_bf16(float4& a, uint2 u) {
    a.x += bf_lo(u.x); a.y += bf_hi(u.x);
    a.z += bf_lo(u.y); a.w += bf_hi(u.y);
}
__device__ __forceinline__ void red_v4(float* p, float4 v) {
    asm volatile("red.global.add.v4.f32 [%0], {%1,%2,%3,%4};"
                 :: "l"(p), "f"(v.x), "f"(v.y), "f"(v.z), "f"(v.w) : "memory");
}

// ---------------- launch 1: degree count + zero w/pool/cnt/counter ----------------
__global__ void k_degree(const int* __restrict__ src, const int* __restrict__ dst, int E) {
    int i0 = blockIdx.x * blockDim.x + threadIdx.x;
    int stride = gridDim.x * blockDim.x;
    float4 z = make_float4(0.f, 0.f, 0.f, 0.f);
    for (int i = i0; i < NN * GG / 4; i += stride) ((float4*)g_w)[i] = z;
    for (int i = i0; i < GG * DD; i += stride) g_pool[i] = 0.f;
    if (i0 < GG) g_cnt[i0] = 0.f;
    if (i0 == GG) g_counter = 0;
    for (int i = i0; i < E; i += stride) {
        atomicAdd(&g_deg[src[i]], 1);
        atomicAdd(&g_deg[NN + dst[i]], 1);
    }
}

// ---------------- launch 2: norms, gd pack, counts, offsets + W1->tf32 ----------------
__global__ void k_nodeprep(const int* __restrict__ gid, const float* __restrict__ W1, int N) {
    int i = blockIdx.x * blockDim.x + threadIdx.x;
    if (i < DD * DD) g_w1t[i] = f2tf32(W1[i]);
    if (i < N) {
        int dout = g_deg[i];
        int din = g_deg[NN + i];
        float ns = rsqrtf((float)max(dout, 1));
        float nd = rsqrtf((float)max(din, 1));
        g_nsrc[i] = ns;
        g_ndst[i] = nd;
        int g = gid[i];
        g_gd[i] = make_uint2((unsigned)g, __float_as_uint(nd));
        atomicAdd(&g_cnt[g], 1.f);
        int off = atomicAdd(&g_counter, din);   // arbitrary-order segment assignment
        g_off[i] = off;
        g_cursor[i] = off;
    }
}

// ---------------- launch 3: scatter + wbuild (edges) and bf16 prep (nodes) ----------------
__global__ void k_edge_node(const int* __restrict__ src, const int* __restrict__ dst,
                            const float* __restrict__ x, int E, int N) {
    int i = blockIdx.x * blockDim.x + threadIdx.x;
    if (i < E) {
        int s = src[i];
        int d = dst[i];
        int p = atomicAdd(&g_cursor[d], 1);
        g_sorted[p] = s;
        uint2 gd = g_gd[d];
        atomicAdd(&g_w[(size_t)s * GG + gd.x], __uint_as_float(gd.y));
    } else {
        int j = i - E;                       // float4 index over node features
        if (j < N * 32) {
            int n = j >> 5;
            float sc = g_nsrc[n];
            float4 v = ((const float4*)x)[j];
            uint2 u;
            u.x = pack_bf16x2(v.x * sc, v.y * sc);
            u.y = pack_bf16x2(v.z * sc, v.w * sc);
            ((uint2*)g_xh)[j] = u;
        }
    }
}

// ---------------- launch 4 (PROFILED): SpMM layer 1 ----------------
__global__ void __launch_bounds__(256) k_spmm1(int N) {
    int warp = (blockIdx.x * blockDim.x + threadIdx.x) >> 5;
    if (warp >= N) return;
    int lane = threadIdx.x & 31;
    const uint2* xh = (const uint2*)g_xh;
    int e0 = g_off[warp];
    int e1 = e0 + g_deg[NN + warp];
    float4 acc = make_float4(0.f, 0.f, 0.f, 0.f);
    for (int base = e0; base < e1; base += 32) {
        int nrem = e1 - base;
        int idx = (lane < nrem) ? g_sorted[base + lane] : 0;
        int m = min(32, nrem);
        int j = 0;
        for (; j + 8 <= m; j += 8) {
            uint2 u[8];
#pragma unroll
            for (int q = 0; q < 8; q++) {
                int s = __shfl_sync(0xffffffffu, idx, j + q);
                u[q] = xh[(size_t)s * 32 + lane];
            }
#pragma unroll
            for (int q = 0; q < 8; q++) acc_bf16(acc, u[q]);
        }
        for (; j < m; j++) {
            int s = __shfl_sync(0xffffffffu, idx, j);
            acc_bf16(acc, xh[(size_t)s * 32 + lane]);
        }
    }
    *(float4*)(g_agg + (size_t)warp * DD + lane * 4) = acc;
}

// ---------------- launch 5: dense stage 1 (tf32 MMA) ----------------
__global__ void __launch_bounds__(256) k_gemm1(const float* __restrict__ b, int N) {
    extern __shared__ unsigned smem[];
    unsigned* sA = smem;               // 64 x SA_ST tf32
    unsigned* sW = smem + 64 * SA_ST;  // 128 x SW_ST tf32

    int t = threadIdx.x;
    int row0 = blockIdx.x * 64;
    int wid = t >> 5;
    int lane = t & 31;

#pragma unroll
    for (int i = 0; i < 16; i++) {
        int f = t + i * 256;
        int r = f >> 5;
        int c = f & 31;
        uint4 v = *(const uint4*)(g_w1t + r * 128 + c * 4);
        *(uint4*)(sW + r * SW_ST + c * 4) = v;
    }
#pragma unroll
    for (int i = 0; i < 8; i++) {
        int f = t + i * 256;
        int r = f >> 5;
        int c = f & 31;
        int row = row0 + r;
        uint4 o = make_uint4(0u, 0u, 0u, 0u);
        if (row < N) {
            float4 v = *(const float4*)(g_agg + (size_t)row * DD + c * 4);
            float s = g_ndst[row];
            o.x = f2tf32(v.x * s); o.y = f2tf32(v.y * s);
            o.z = f2tf32(v.z * s); o.w = f2tf32(v.w * s);
        }
        *(uint4*)(sA + r * SA_ST + c * 4) = o;
    }
    __syncthreads();

    int g = lane >> 2;
    int tg = lane & 3;
    int wm = wid >> 2;
    int wn = wid & 3;

    float acc[2][4][4];
#pragma unroll
    for (int i = 0; i < 2; i++)
#pragma unroll
        for (int j = 0; j < 4; j++)
#pragma unroll
            for (int q = 0; q < 4; q++) acc[i][j][q] = 0.f;

    const unsigned* pA = sA + (wm * 32 + g) * SA_ST + tg;
    const unsigned* pB = sW + tg * SW_ST + wn * 32 + g;

#pragma unroll
    for (int ks = 0; ks < 16; ks++) {
        int k0 = ks * 8;
        unsigned a[2][4];
#pragma unroll
        for (int i = 0; i < 2; i++) {
            const unsigned* p = pA + i * 16 * SA_ST + k0;
            a[i][0] = p[0];
            a[i][1] = p[8 * SA_ST];
            a[i][2] = p[4];
            a[i][3] = p[8 * SA_ST + 4];
        }
        unsigned bb[4][2];
#pragma unroll
        for (int j = 0; j < 4; j++) {
            const unsigned* p = pB + k0 * SW_ST + j * 8;
            bb[j][0] = p[0];
            bb[j][1] = p[4 * SW_ST];
        }
#pragma unroll
        for (int i = 0; i < 2; i++)
#pragma unroll
            for (int j = 0; j < 4; j++)
                mma_tf32(acc[i][j][0], acc[i][j][1], acc[i][j][2], acc[i][j][3],
                         a[i][0], a[i][1], a[i][2], a[i][3], bb[j][0], bb[j][1]);
    }

#pragma unroll
    for (int i = 0; i < 2; i++) {
        int rA = row0 + wm * 32 + i * 16 + g;
        int rB = rA + 8;
        float sA_ = (rA < N) ? g_nsrc[rA] : 0.f;
        float sB_ = (rB < N) ? g_nsrc[rB] : 0.f;
#pragma unroll
        for (int j = 0; j < 4; j++) {
            int c = wn * 32 + j * 8 + tg * 2;
            float bx = b[c], by = b[c + 1];
            if (rA < N) {
                float x0 = fmaxf(acc[i][j][0] + bx, 0.f) * sA_;
                float x1 = fmaxf(acc[i][j][1] + by, 0.f) * sA_;
                g_xh2[(size_t)rA * 64 + (c >> 1)] = pack_bf16x2(x0, x1);
            }
            if (rB < N) {
                float x2 = fmaxf(acc[i][j][2] + bx, 0.f) * sB_;
                float x3 = fmaxf(acc[i][j][3] + by, 0.f) * sB_;
                g_xh2[(size_t)rB * 64 + (c >> 1)] = pack_bf16x2(x2, x3);
            }
        }
    }
}

// ---------------- launch 6: gemm2 (tf32 MMA, K-chunk=64 nodes) ----------------
// P[g(64)][d(128)] = sum_n w[n][g] * xh2[n][d]
// smem overlay: [sw 64xST_W | sx 64xST_X] reused as spool (8192 floats) at the end.
#define G2_K 64
__global__ void __launch_bounds__(256) k_gemm2(int N) {
    __shared__ float smem_raw[G2_K * ST_W + G2_K * ST_X];  // 33.5KB
    float*    sw = smem_raw;                    // [k][g]
    unsigned* sx = (unsigned*)(smem_raw + G2_K * ST_W);  // [k][word]
    float*    spool = smem_raw;                 // overlay for output staging

    int t = threadIdx.x;
    int wid = t >> 5;
    int lane = t & 31;
    int g = lane >> 2;
    int tg = lane & 3;
    int wm = wid >> 1;       // 0..3  -> m tile = wm*16
    int wn = wid & 1;        // 0..1  -> dims wn*64 ..

    int chunk = (N + NB2 - 1) / NB2;
    int nb0 = blockIdx.x * chunk;
    int nend = min(nb0 + chunk, N);

    float acc[8][4];
#pragma unroll
    for (int j = 0; j < 8; j++)
#pragma unroll
        for (int q = 0; q < 4; q++) acc[j][q] = 0.f;

    for (int nb = nb0; nb < nend; nb += G2_K) {
        // stage 64 nodes: 16 w-words + 16 x-words per thread, coalesced
#pragma unroll
        for (int i = 0; i < 16; i++) {
            int word = t + i * 256;           // 0..4095
            int k = word >> 6, col = word & 63;
            int n = nb + k;
            bool ok = (n < nend);
            sw[k * ST_W + col] = ok ? g_w[(size_t)n * GG + col] : 0.f;
            sx[k * ST_X + col] = ok ? g_xh2[(size_t)n * 64 + col] : 0u;
        }
        __syncthreads();

#pragma unroll
        for (int ks = 0; ks < G2_K / 8; ks++) {
            int k0 = ks * 8;
            // A frag: A[m=graph][k]
            unsigned a0 = f2tf32(sw[(k0 + tg) * ST_W + wm * 16 + g]);
            unsigned a1 = f2tf32(sw[(k0 + tg) * ST_W + wm * 16 + g + 8]);
            unsigned a2 = f2tf32(sw[(k0 + tg + 4) * ST_W + wm * 16 + g]);
            unsigned a3 = f2tf32(sw[(k0 + tg + 4) * ST_W + wm * 16 + g + 8]);
#pragma unroll
            for (int j = 0; j < 8; j++) {
                int nj = wn * 64 + j * 8;            // dim base
                int wrd = (nj >> 1) + (g >> 1);      // bf16x2 word index
                unsigned u0 = sx[(k0 + tg) * ST_X + wrd];
                unsigned u1 = sx[(k0 + tg + 4) * ST_X + wrd];
                unsigned b0 = (g & 1) ? (u0 & 0xffff0000u) : (u0 << 16);
                unsigned b1 = (g & 1) ? (u1 & 0xffff0000u) : (u1 << 16);
                mma_tf32(acc[j][0], acc[j][1], acc[j][2], acc[j][3],
                         a0, a1, a2, a3, b0, b1);
            }
        }
        __syncthreads();
    }

    // stage tile to smem overlay, then vector-reduce to g_pool
#pragma unroll
    for (int j = 0; j < 8; j++) {
        int nj = wn * 64 + j * 8 + tg * 2;
        int r = wm * 16 + g;
        spool[r * DD + nj] = acc[j][0];
        spool[r * DD + nj + 1] = acc[j][1];
        spool[(r + 8) * DD + nj] = acc[j][2];
        spool[(r + 8) * DD + nj + 1] = acc[j][3];
    }
    __syncthreads();
#pragma unroll
    for (int i = 0; i < 8; i++) {
        int q = t + i * 256;                 // 0..2047 float4s
        float4 v = ((float4*)spool)[q];
        red_v4(g_pool + q * 4, v);
    }
}

// ---------------- launch 7: out = (g_pool/cnt) @ W2 + b2 ----------------
__global__ void k_final(const float* __restrict__ W2, const float* __restrict__ b2,
                        float* __restrict__ out) {
    __shared__ float srow[DD];
    int g = blockIdx.x, t = threadIdx.x;
    srow[t] = g_pool[g * DD + t] / fmaxf(g_cnt[g], 1.f);
    __syncthreads();
    float a = b2[t];
#pragma unroll 8
    for (int k = 0; k < DD; k++) a += srow[k] * W2[k * DD + t];
    out[g * DD + t] = a;
}

// ---------------- launch ----------------
extern "C" void kernel_launch(void* const* d_in, const int* in_sizes, int n_in,
                              void* d_out, int out_size) {
    const float* in_feat = (const float*)d_in[0];
    const float* W1 = (const float*)d_in[1];
    const float* b1 = (const float*)d_in[2];
    const float* W2 = (const float*)d_in[3];
    const float* b2 = (const float*)d_in[4];
    const int* src = (const int*)d_in[5];
    const int* dst = (const int*)d_in[6];
    const int* gid = (const int*)d_in[7];
    int N = in_sizes[0] / DD;
    int E = in_sizes[5];
    (void)n_in; (void)out_size;

    void* p_deg;
    cudaGetSymbolAddress(&p_deg, g_deg);

    const int gemm_smem = (64 * SA_ST + 128 * SW_ST) * (int)sizeof(unsigned);
    static int smem_set = 0;
    if (!smem_set) {
        cudaFuncSetAttribute(k_gemm1, cudaFuncAttributeMaxDynamicSharedMemorySize, gemm_smem);
        smem_set = 1;
    }

    cudaMemsetAsync(p_deg, 0, 2 * NN * sizeof(int));

    k_degree<<<1024, 256>>>(src, dst, E);                                     // 1
    k_nodeprep<<<(N + 255) / 256, 256>>>(gid, W1, N);                         // 2
    k_edge_node<<<(E + N * 32 + 255) / 256, 256>>>(src, dst, in_feat, E, N);  // 3
    k_spmm1<<<(N + 7) / 8, 256>>>(N);                                         // 4 <- profiled
    k_gemm1<<<(N + 63) / 64, 256, gemm_smem>>>(b1, N);                        // 5
    k_gemm2<<<NB2, 256>>>(N);                                                 // 6
    k_final<<<GG, DD>>>(W2, b2, (float*)d_out);                               // 7
}

// round 15
// speedup vs baseline: 1.2921x; 1.1039x over previous
#include <cuda_runtime.h>
#include <cuda_bf16.h>
#include <cstdint>

#define NN 100000
#define EE 1600000
#define DD 128
#define GG 64
#define NB2 148          // gemm2 blocks

#define A_ST 68          // gemm1 A tile stride (f16x2 words)
#define W_ST 136         // gemm1 W tile stride (f16x2 words)
#define ST_W 65
#define ST_X 66

// ---------------- device scratch ----------------
__device__ float    g_agg[(size_t)NN * DD];      // spmm1 output (fp32)
__device__ unsigned g_xh[(size_t)NN * DD / 2];   // bf16x2 scaled input features
__device__ unsigned g_xh2[(size_t)NN * DD / 2];  // bf16x2 layer-1 output
__device__ float    g_w[(size_t)NN * GG];        // per-(src,graph) pooling weights
__device__ unsigned g_w1h[DD / 2 * DD];          // W1 packed f16x2 along k: [k/2][n]
__device__ float    g_pool[GG * DD];             // pooled sums (red target)
__device__ uint2    g_gd[NN];                    // packed {gid, ndst}
__device__ int      g_deg[2 * NN];               // [0,NN)=deg_out, [NN,2NN)=deg_in
__device__ float    g_nsrc[NN];
__device__ float    g_ndst[NN];
__device__ float    g_cnt[GG];
__device__ int      g_off[NN];
__device__ int      g_cursor[NN];
__device__ int      g_sorted[EE];
__device__ int      g_counter;

// ---------------- helpers ----------------
__device__ __forceinline__ unsigned f2tf32(float x) {
    unsigned r;
    asm("cvt.rna.tf32.f32 %0, %1;" : "=r"(r) : "f"(x));
    return r;
}
__device__ __forceinline__ unsigned pack_bf16x2(float lo, float hi) {
    unsigned r;
    asm("cvt.rn.bf16x2.f32 %0, %1, %2;" : "=r"(r) : "f"(hi), "f"(lo));
    return r;
}
__device__ __forceinline__ unsigned pack_f16x2(float lo, float hi) {
    unsigned r;
    asm("cvt.rn.f16x2.f32 %0, %1, %2;" : "=r"(r) : "f"(hi), "f"(lo));
    return r;
}
__device__ __forceinline__ void mma_tf32(float& d0, float& d1, float& d2, float& d3,
                                         unsigned a0, unsigned a1, unsigned a2, unsigned a3,
                                         unsigned b0, unsigned b1) {
    asm("mma.sync.aligned.m16n8k8.row.col.f32.tf32.tf32.f32 "
        "{%0,%1,%2,%3}, {%4,%5,%6,%7}, {%8,%9}, {%0,%1,%2,%3};"
        : "+f"(d0), "+f"(d1), "+f"(d2), "+f"(d3)
        : "r"(a0), "r"(a1), "r"(a2), "r"(a3), "r"(b0), "r"(b1));
}
__device__ __forceinline__ void mma_f16(float& d0, float& d1, float& d2, float& d3,
                                        unsigned a0, unsigned a1, unsigned a2, unsigned a3,
                                        unsigned b0, unsigned b1) {
    asm("mma.sync.aligned.m16n8k16.row.col.f32.f16.f16.f32 "
        "{%0,%1,%2,%3}, {%4,%5,%6,%7}, {%8,%9}, {%0,%1,%2,%3};"
        : "+f"(d0), "+f"(d1), "+f"(d2), "+f"(d3)
        : "r"(a0), "r"(a1), "r"(a2), "r"(a3), "r"(b0), "r"(b1));
}
__device__ __forceinline__ float bf_lo(unsigned u) { return __uint_as_float(u << 16); }
__device__ __forceinline__ float bf_hi(unsigned u) { return __uint_as_float(u & 0xffff0000u); }
__device__ __forceinline__ void acc_bf16(float4& a, uint2 u) {
    a.x += bf_lo(u.x); a.y += bf_hi(u.x);
    a.z += bf_lo(u.y); a.w += bf_hi(u.y);
}
__device__ __forceinline__ void red_v4(float* p, float4 v) {
    asm volatile("red.global.add.v4.f32 [%0], {%1,%2,%3,%4};"
                 :: "l"(p), "f"(v.x), "f"(v.y), "f"(v.z), "f"(v.w) : "memory");
}

// ---------------- launch 1: degree count + zero w/pool/cnt/counter ----------------
__global__ void k_degree(const int* __restrict__ src, const int* __restrict__ dst, int E) {
    int i0 = blockIdx.x * blockDim.x + threadIdx.x;
    int stride = gridDim.x * blockDim.x;
    float4 z = make_float4(0.f, 0.f, 0.f, 0.f);
    for (int i = i0; i < NN * GG / 4; i += stride) ((float4*)g_w)[i] = z;
    for (int i = i0; i < GG * DD; i += stride) g_pool[i] = 0.f;
    if (i0 < GG) g_cnt[i0] = 0.f;
    if (i0 == GG) g_counter = 0;
    for (int i = i0; i < E; i += stride) {
        atomicAdd(&g_deg[src[i]], 1);
        atomicAdd(&g_deg[NN + dst[i]], 1);
    }
}

// ---------------- launch 2: norms, gd pack, counts, offsets + W1->f16x2 ----------------
__global__ void k_nodeprep(const int* __restrict__ gid, const float* __restrict__ W1, int N) {
    int i = blockIdx.x * blockDim.x + threadIdx.x;
    if (i < DD / 2 * DD) {
        int m = i >> 7;            // k-pair index
        int n = i & 127;
        g_w1h[i] = pack_f16x2(W1[(2 * m) * DD + n], W1[(2 * m + 1) * DD + n]);
    }
    if (i < N) {
        int dout = g_deg[i];
        int din = g_deg[NN + i];
        float ns = rsqrtf((float)max(dout, 1));
        float nd = rsqrtf((float)max(din, 1));
        g_nsrc[i] = ns;
        g_ndst[i] = nd;
        int g = gid[i];
        g_gd[i] = make_uint2((unsigned)g, __float_as_uint(nd));
        atomicAdd(&g_cnt[g], 1.f);
        int off = atomicAdd(&g_counter, din);   // arbitrary-order segment assignment
        g_off[i] = off;
        g_cursor[i] = off;
    }
}

// ---------------- launch 3: scatter + wbuild (edges) and bf16 prep (nodes) ----------------
__global__ void k_edge_node(const int* __restrict__ src, const int* __restrict__ dst,
                            const float* __restrict__ x, int E, int N) {
    int i = blockIdx.x * blockDim.x + threadIdx.x;
    if (i < E) {
        int s = src[i];
        int d = dst[i];
        int p = atomicAdd(&g_cursor[d], 1);
        g_sorted[p] = s;
        uint2 gd = g_gd[d];
        atomicAdd(&g_w[(size_t)s * GG + gd.x], __uint_as_float(gd.y));
    } else {
        int j = i - E;                       // float4 index over node features
        if (j < N * 32) {
            int n = j >> 5;
            float sc = g_nsrc[n];
            float4 v = ((const float4*)x)[j];
            uint2 u;
            u.x = pack_bf16x2(v.x * sc, v.y * sc);
            u.y = pack_bf16x2(v.z * sc, v.w * sc);
            ((uint2*)g_xh)[j] = u;
        }
    }
}

// ---------------- launch 4 (PROFILED): SpMM layer 1 ----------------
__global__ void __launch_bounds__(256) k_spmm1(int N) {
    int warp = (blockIdx.x * blockDim.x + threadIdx.x) >> 5;
    if (warp >= N) return;
    int lane = threadIdx.x & 31;
    const uint2* xh = (const uint2*)g_xh;
    int e0 = g_off[warp];
    int e1 = e0 + g_deg[NN + warp];
    float4 acc = make_float4(0.f, 0.f, 0.f, 0.f);
    for (int base = e0; base < e1; base += 32) {
        int nrem = e1 - base;
        int idx = (lane < nrem) ? g_sorted[base + lane] : 0;
        int m = min(32, nrem);
        int j = 0;
        for (; j + 8 <= m; j += 8) {
            uint2 u[8];
#pragma unroll
            for (int q = 0; q < 8; q++) {
                int s = __shfl_sync(0xffffffffu, idx, j + q);
                u[q] = xh[(size_t)s * 32 + lane];
            }
#pragma unroll
            for (int q = 0; q < 8; q++) acc_bf16(acc, u[q]);
        }
        for (; j < m; j++) {
            int s = __shfl_sync(0xffffffffu, idx, j);
            acc_bf16(acc, xh[(size_t)s * 32 + lane]);
        }
    }
    *(float4*)(g_agg + (size_t)warp * DD + lane * 4) = acc;
}

// ---------------- launch 5: dense stage 1 (fp16 m16n8k16 MMA) ----------------
// g_xh2 = bf16( relu((g_agg*ndst) @ W1 + b1) * nsrc ); A,W in fp16, accum fp32.
__global__ void __launch_bounds__(256) k_gemm1(const float* __restrict__ b, int N) {
    __shared__ unsigned sA[64 * A_ST];   // f16x2 words: [row][k/2]
    __shared__ unsigned sW[64 * W_ST];   // f16x2 words: [k/2][n]

    int t = threadIdx.x;
    int row0 = blockIdx.x * 64;
    int wid = t >> 5;
    int lane = t & 31;

    // stage W: 8192 words = 2048 uint4, 8 per thread
#pragma unroll
    for (int i = 0; i < 8; i++) {
        int q = t + i * 256;
        int r = q >> 5;          // k-pair row (32 uint4 per row)
        int c = q & 31;
        uint4 v = ((const uint4*)g_w1h)[q];
        *(uint4*)(sW + r * W_ST + c * 4) = v;
    }
    // stage A: 4096 words (64 rows x 64), 16 per thread; scale by ndst, cvt fp16x2
#pragma unroll
    for (int i = 0; i < 16; i++) {
        int q = t + i * 256;
        int r = q >> 6;
        int c = q & 63;          // k-pair index
        int row = row0 + r;
        unsigned o = 0u;
        if (row < N) {
            float2 v = *(const float2*)(g_agg + (size_t)row * DD + c * 2);
            float s = g_ndst[row];
            o = pack_f16x2(v.x * s, v.y * s);
        }
        sA[r * A_ST + c] = o;
    }
    __syncthreads();

    int g = lane >> 2;
    int tg = lane & 3;
    int wm = wid >> 2;
    int wn = wid & 3;

    float acc[2][4][4];
#pragma unroll
    for (int i = 0; i < 2; i++)
#pragma unroll
        for (int j = 0; j < 4; j++)
#pragma unroll
            for (int q = 0; q < 4; q++) acc[i][j][q] = 0.f;

#pragma unroll
    for (int ks = 0; ks < 8; ks++) {
        int kw = ks * 8;    // k-pair word base
        unsigned a[2][4];
#pragma unroll
        for (int i = 0; i < 2; i++) {
            int rA = (wm * 32 + i * 16 + g) * A_ST + kw;
            int rB = (wm * 32 + i * 16 + g + 8) * A_ST + kw;
            a[i][0] = sA[rA + tg];
            a[i][1] = sA[rB + tg];
            a[i][2] = sA[rA + tg + 4];
            a[i][3] = sA[rB + tg + 4];
        }
        unsigned bb[4][2];
#pragma unroll
        for (int j = 0; j < 4; j++) {
            int n = wn * 32 + j * 8 + g;
            bb[j][0] = sW[(kw + tg) * W_ST + n];
            bb[j][1] = sW[(kw + tg + 4) * W_ST + n];
        }
#pragma unroll
        for (int i = 0; i < 2; i++)
#pragma unroll
            for (int j = 0; j < 4; j++)
                mma_f16(acc[i][j][0], acc[i][j][1], acc[i][j][2], acc[i][j][3],
                        a[i][0], a[i][1], a[i][2], a[i][3], bb[j][0], bb[j][1]);
    }

    // epilogue: +bias, relu, *nsrc, bf16 pack -> g_xh2
#pragma unroll
    for (int i = 0; i < 2; i++) {
        int rA = row0 + wm * 32 + i * 16 + g;
        int rB = rA + 8;
        float sA_ = (rA < N) ? g_nsrc[rA] : 0.f;
        float sB_ = (rB < N) ? g_nsrc[rB] : 0.f;
#pragma unroll
        for (int j = 0; j < 4; j++) {
            int c = wn * 32 + j * 8 + tg * 2;
            float bx = b[c], by = b[c + 1];
            if (rA < N) {
                float x0 = fmaxf(acc[i][j][0] + bx, 0.f) * sA_;
                float x1 = fmaxf(acc[i][j][1] + by, 0.f) * sA_;
                g_xh2[(size_t)rA * 64 + (c >> 1)] = pack_bf16x2(x0, x1);
            }
            if (rB < N) {
                float x2 = fmaxf(acc[i][j][2] + bx, 0.f) * sB_;
                float x3 = fmaxf(acc[i][j][3] + by, 0.f) * sB_;
                g_xh2[(size_t)rB * 64 + (c >> 1)] = pack_bf16x2(x2, x3);
            }
        }
    }
}

// ---------------- launch 6: gemm2 (tf32 MMA, K-chunk=64 nodes) ----------------
#define G2_K 64
__global__ void __launch_bounds__(256) k_gemm2(int N) {
    __shared__ float smem_raw[G2_K * ST_W + G2_K * ST_X];  // 33.5KB
    float*    sw = smem_raw;                    // [k][g]
    unsigned* sx = (unsigned*)(smem_raw + G2_K * ST_W);  // [k][word]
    float*    spool = smem_raw;                 // overlay for output staging

    int t = threadIdx.x;
    int wid = t >> 5;
    int lane = t & 31;
    int g = lane >> 2;
    int tg = lane & 3;
    int wm = wid >> 1;
    int wn = wid & 1;

    int chunk = (N + NB2 - 1) / NB2;
    int nb0 = blockIdx.x * chunk;
    int nend = min(nb0 + chunk, N);

    float acc[8][4];
#pragma unroll
    for (int j = 0; j < 8; j++)
#pragma unroll
        for (int q = 0; q < 4; q++) acc[j][q] = 0.f;

    for (int nb = nb0; nb < nend; nb += G2_K) {
#pragma unroll
        for (int i = 0; i < 16; i++) {
            int word = t + i * 256;
            int k = word >> 6, col = word & 63;
            int n = nb + k;
            bool ok = (n < nend);
            sw[k * ST_W + col] = ok ? g_w[(size_t)n * GG + col] : 0.f;
            sx[k * ST_X + col] = ok ? g_xh2[(size_t)n * 64 + col] : 0u;
        }
        __syncthreads();

#pragma unroll
        for (int ks = 0; ks < G2_K / 8; ks++) {
            int k0 = ks * 8;
            unsigned a0 = f2tf32(sw[(k0 + tg) * ST_W + wm * 16 + g]);
            unsigned a1 = f2tf32(sw[(k0 + tg) * ST_W + wm * 16 + g + 8]);
            unsigned a2 = f2tf32(sw[(k0 + tg + 4) * ST_W + wm * 16 + g]);
            unsigned a3 = f2tf32(sw[(k0 + tg + 4) * ST_W + wm * 16 + g + 8]);
#pragma unroll
            for (int j = 0; j < 8; j++) {
                int nj = wn * 64 + j * 8;
                int wrd = (nj >> 1) + (g >> 1);
                unsigned u0 = sx[(k0 + tg) * ST_X + wrd];
                unsigned u1 = sx[(k0 + tg + 4) * ST_X + wrd];
                unsigned b0 = (g & 1) ? (u0 & 0xffff0000u) : (u0 << 16);
                unsigned b1 = (g & 1) ? (u1 & 0xffff0000u) : (u1 << 16);
                mma_tf32(acc[j][0], acc[j][1], acc[j][2], acc[j][3],
                         a0, a1, a2, a3, b0, b1);
            }
        }
        __syncthreads();
    }

#pragma unroll
    for (int j = 0; j < 8; j++) {
        int nj = wn * 64 + j * 8 + tg * 2;
        int r = wm * 16 + g;
        spool[r * DD + nj] = acc[j][0];
        spool[r * DD + nj + 1] = acc[j][1];
        spool[(r + 8) * DD + nj] = acc[j][2];
        spool[(r + 8) * DD + nj + 1] = acc[j][3];
    }
    __syncthreads();
#pragma unroll
    for (int i = 0; i < 8; i++) {
        int q = t + i * 256;
        float4 v = ((float4*)spool)[q];
        red_v4(g_pool + q * 4, v);
    }
}

// ---------------- launch 7: out = (g_pool/cnt) @ W2 + b2 ----------------
__global__ void k_final(const float* __restrict__ W2, const float* __restrict__ b2,
                        float* __restrict__ out) {
    __shared__ float srow[DD];
    int g = blockIdx.x, t = threadIdx.x;
    srow[t] = g_pool[g * DD + t] / fmaxf(g_cnt[g], 1.f);
    __syncthreads();
    float a = b2[t];
#pragma unroll 8
    for (int k = 0; k < DD; k++) a += srow[k] * W2[k * DD + t];
    out[g * DD + t] = a;
}

// ---------------- launch ----------------
extern "C" void kernel_launch(void* const* d_in, const int* in_sizes, int n_in,
                              void* d_out, int out_size) {
    const float* in_feat = (const float*)d_in[0];
    const float* W1 = (const float*)d_in[1];
    const float* b1 = (const float*)d_in[2];
    const float* W2 = (const float*)d_in[3];
    const float* b2 = (const float*)d_in[4];
    const int* src = (const int*)d_in[5];
    const int* dst = (const int*)d_in[6];
    const int* gid = (const int*)d_in[7];
    int N = in_sizes[0] / DD;
    int E = in_sizes[5];
    (void)n_in; (void)out_size;

    void* p_deg;
    cudaGetSymbolAddress(&p_deg, g_deg);

    cudaMemsetAsync(p_deg, 0, 2 * NN * sizeof(int));

    k_degree<<<1024, 256>>>(src, dst, E);                                     // 1
    k_nodeprep<<<(N + 255) / 256, 256>>>(gid, W1, N);                         // 2
    k_edge_node<<<(E + N * 32 + 255) / 256, 256>>>(src, dst, in_feat, E, N);  // 3
    k_spmm1<<<(N + 7) / 8, 256>>>(N);                                         // 4 <- profiled
    k_gemm1<<<(N + 63) / 64, 256>>>(b1, N);                                   // 5
    k_gemm2<<<NB2, 256>>>(N);                                                 // 6
    k_final<<<GG, DD>>>(W2, b2, (float*)d_out);                               // 7
}